// round 14
// baseline (speedup 1.0000x reference)
#include <cuda_runtime.h>
#include <stdint.h>
#include <stddef.h>

// ---------------------------------------------------------------------------
// MeshMultiHeadHodgeAttentionVertices — fp32 exact implementation
//
// Shapes: B=2, N=4096, M=12288, H=8, D=256 (dk=32), KV=KE=16
// Layout convention: every activation is (batch, rows, 256) row-major with
// column c = h*32 + d  (== split_heads column block). This makes LayerNorm
// (per 32-col block), sparse attention (per 32-col block) and the final
// transpose+reshape all trivial.
//
// Pipeline:
//   1) vQ,vK,vV = x_v @ W^T   (GEMM, TB)     rows = B*N = 8192
//      eQ,eK    = x_e @ W^T   (GEMM, TB)     rows = B*M = 24576
//   2) LayerNorm(32) in-place on vQ,vK,eQ,eK
//   3) y1[b] = d0[b] @ vV[b]                 (GEMM NN, K=4096)
//   4) y2 = sparse_attn(q=eQ, k=eK, v=y1, e_idx)
//   5) z1[b] = d0[b]^T @ y2[b]               (GEMM TA, K=12288)
//   6) out = sparse_attn(q=vK, k=vQ, v=z1, v_idx)
//
// GEMM core: 128x128x8 tile, 256 threads, 8x8 per thread, accumulation via
// packed fma.rn.f32x2 (FFMA2) -> 2x the fp32 FFMA rate on sm_103a.
// ---------------------------------------------------------------------------

#define B_SZ 2
#define N_SZ 4096
#define M_SZ 12288
#define D_SZ 256

// scratch offsets (floats)
#define OFF_VQ 0ull
#define OFF_VK 2097152ull       //  B*N*256
#define OFF_VV 4194304ull
#define OFF_EQ 6291456ull       //  then B*M*256 blocks
#define OFF_EK 12582912ull
#define OFF_Y1 18874368ull
#define OFF_Y2 25165824ull
#define OFF_Z1 31457280ull
#define SCRATCH_FLOATS 33554432ull   // 128 MiB

__device__ float g_scratch[SCRATCH_FLOATS];

// ---- packed fp32x2 helpers (sm_103a FFMA2 via PTX) ------------------------
__device__ __forceinline__ unsigned long long splat2(float a) {
    unsigned int u = __float_as_uint(a);
    unsigned long long r;
    asm("mov.b64 %0, {%1, %1};" : "=l"(r) : "r"(u));
    return r;
}
__device__ __forceinline__ unsigned long long ffma2(unsigned long long a,
                                                    unsigned long long b,
                                                    unsigned long long c) {
    unsigned long long d;
    asm("fma.rn.f32x2 %0, %1, %2, %3;" : "=l"(d) : "l"(a), "l"(b), "l"(c));
    return d;
}

// ---------------------------------------------------------------------------
// Tiled GEMM:  C[i,j] = sum_k Aop[i,k] * Bop[k,j]
//   TA=false: A row-major (i,k), lda = row stride
//   TA=true : A stored (k,i), lda = stride per k  (i.e. C = A^T_storage @ B)
//   TB=false: B row-major (k,j), ldb = row stride
//   TB=true : B stored (j,k), ldb = row stride    (i.e. B = W^T)
// All dims must be multiples of the tile (they are, by construction).
// ---------------------------------------------------------------------------
template <bool TA, bool TB>
__global__ __launch_bounds__(256, 2)
void sgemm_kernel(const float* __restrict__ A, const float* __restrict__ B,
                  float* __restrict__ C, int K, int lda, int ldb, int ldc,
                  size_t sA, size_t sB, size_t sC)
{
    __shared__ float As[8][132];
    __shared__ float Bs[8][132];

    A += (size_t)blockIdx.z * sA;
    B += (size_t)blockIdx.z * sB;
    C += (size_t)blockIdx.z * sC;

    const int i0 = blockIdx.y * 128;
    const int j0 = blockIdx.x * 128;
    const int tid = threadIdx.x;
    const int tx = tid & 15;   // col group
    const int ty = tid >> 4;   // row group

    // acc[m][n] packs output pair (col even, col odd)
    unsigned long long acc[8][4];
#pragma unroll
    for (int m = 0; m < 8; ++m)
#pragma unroll
        for (int n = 0; n < 4; ++n) acc[m][n] = 0ull;

    for (int k0 = 0; k0 < K; k0 += 8) {
        // ---- load A tile (128 rows x 8 k) into As[k][row] ----
        if (!TA) {
            const int row = tid >> 1;
            const int kq  = (tid & 1) * 4;
            float4 av = *reinterpret_cast<const float4*>(
                A + (size_t)(i0 + row) * lda + k0 + kq);
            As[kq + 0][row] = av.x;
            As[kq + 1][row] = av.y;
            As[kq + 2][row] = av.z;
            As[kq + 3][row] = av.w;
        } else {
            const int kk = tid >> 5;
            const int ii = (tid & 31) * 4;
            *reinterpret_cast<float4*>(&As[kk][ii]) =
                *reinterpret_cast<const float4*>(
                    A + (size_t)(k0 + kk) * lda + i0 + ii);
        }
        // ---- load B tile (8 k x 128 cols) into Bs[k][col] ----
        if (!TB) {
            const int kk = tid >> 5;
            const int jj = (tid & 31) * 4;
            *reinterpret_cast<float4*>(&Bs[kk][jj]) =
                *reinterpret_cast<const float4*>(
                    B + (size_t)(k0 + kk) * ldb + j0 + jj);
        } else {
            const int col = tid >> 1;
            const int kq  = (tid & 1) * 4;
            float4 bv = *reinterpret_cast<const float4*>(
                B + (size_t)(j0 + col) * ldb + k0 + kq);
            Bs[kq + 0][col] = bv.x;
            Bs[kq + 1][col] = bv.y;
            Bs[kq + 2][col] = bv.z;
            Bs[kq + 3][col] = bv.w;
        }
        __syncthreads();

#pragma unroll
        for (int kk = 0; kk < 8; ++kk) {
            float4 a0 = *reinterpret_cast<const float4*>(&As[kk][ty * 4]);
            float4 a1 = *reinterpret_cast<const float4*>(&As[kk][64 + ty * 4]);
            ulonglong2 b0 = *reinterpret_cast<const ulonglong2*>(&Bs[kk][tx * 4]);
            ulonglong2 b1 = *reinterpret_cast<const ulonglong2*>(&Bs[kk][64 + tx * 4]);
            float a[8] = {a0.x, a0.y, a0.z, a0.w, a1.x, a1.y, a1.z, a1.w};
            unsigned long long bp[4] = {b0.x, b0.y, b1.x, b1.y};
#pragma unroll
            for (int m = 0; m < 8; ++m) {
                unsigned long long am = splat2(a[m]);
#pragma unroll
                for (int n = 0; n < 4; ++n)
                    acc[m][n] = ffma2(am, bp[n], acc[m][n]);
            }
        }
        __syncthreads();
    }

    // ---- epilogue: pairs are contiguous columns -> 8-byte stores ----
#pragma unroll
    for (int m = 0; m < 8; ++m) {
        const int gi = i0 + ((m < 4) ? (ty * 4 + m) : (64 + ty * 4 + (m - 4)));
#pragma unroll
        for (int n = 0; n < 4; ++n) {
            const int gj = j0 + ((n < 2) ? (tx * 4 + 2 * n)
                                         : (64 + tx * 4 + 2 * (n - 2)));
            *reinterpret_cast<unsigned long long*>(
                C + (size_t)gi * ldc + gj) = acc[m][n];
        }
    }
}

// ---------------------------------------------------------------------------
// Per-head LayerNorm over 32-element blocks, in place.
// One block per row, one warp per head.
// ---------------------------------------------------------------------------
__global__ __launch_bounds__(256)
void ln_heads_kernel(float* __restrict__ x)
{
    const size_t row = blockIdx.x;
    const int h = threadIdx.x >> 5;
    const int d = threadIdx.x & 31;
    float* p = x + row * 256 + h * 32;

    float v = p[d];
    float s = v;
#pragma unroll
    for (int o = 16; o > 0; o >>= 1) s += __shfl_xor_sync(0xffffffffu, s, o);
    const float mu = s * (1.0f / 32.0f);
    const float c = v - mu;
    float s2 = c * c;
#pragma unroll
    for (int o = 16; o > 0; o >>= 1) s2 += __shfl_xor_sync(0xffffffffu, s2, o);
    const float var = s2 * (1.0f / 32.0f);
    p[d] = c * rsqrtf(var + 1e-5f);
}

// ---------------------------------------------------------------------------
// Sparse attention: per (batch, row, head) warp.
//   scores_j = <q[row], k[idx[row][j]]> / sqrt(32);  softmax over 16;
//   out[row] = sum_j w_j * v[idx[row][j]]
// All tensors (B, R, 256) with head = 32-col block. 256 threads = 8 heads.
// ---------------------------------------------------------------------------
__global__ __launch_bounds__(256)
void sparse_attn_kernel(const float* __restrict__ q, const float* __restrict__ k,
                        const float* __restrict__ v, const int* __restrict__ idx,
                        float* __restrict__ out, int R)
{
    const int row = blockIdx.x;
    const size_t base = (size_t)blockIdx.y * (size_t)R * 256u;
    const int h = threadIdx.x >> 5;
    const int d = threadIdx.x & 31;
    const int col = h * 32 + d;

    const float qd = q[base + (size_t)row * 256 + col];

    int   g[16];
    float s[16];
#pragma unroll
    for (int j = 0; j < 16; ++j) {
        g[j] = __ldg(&idx[row * 16 + j]);
        const float kd = k[base + (size_t)g[j] * 256 + col];
        float p = qd * kd;
#pragma unroll
        for (int o = 16; o > 0; o >>= 1) p += __shfl_xor_sync(0xffffffffu, p, o);
        s[j] = p * 0.17677669529663687f;   // 1/sqrt(32)
    }

    float mx = s[0];
#pragma unroll
    for (int j = 1; j < 16; ++j) mx = fmaxf(mx, s[j]);
    float den = 0.0f;
#pragma unroll
    for (int j = 0; j < 16; ++j) { s[j] = expf(s[j] - mx); den += s[j]; }
    const float inv = 1.0f / den;

    float o = 0.0f;
#pragma unroll
    for (int j = 0; j < 16; ++j)
        o += s[j] * v[base + (size_t)g[j] * 256 + col];

    out[base + (size_t)row * 256 + col] = o * inv;
}

// ---------------------------------------------------------------------------
// Host launcher — graph-capturable: kernel launches only, default stream.
// Input order (metadata): x_v, x_e, d_0, W_vQ, W_vK, W_vV, W_eQ, W_eK,
//                         v_idx, e_idx. Output: float32 (B, N, 256).
// ---------------------------------------------------------------------------
extern "C" void kernel_launch(void* const* d_in, const int* in_sizes, int n_in,
                              void* d_out, int out_size)
{
    (void)in_sizes; (void)n_in; (void)out_size;
    const float* x_v  = (const float*)d_in[0];
    const float* x_e  = (const float*)d_in[1];
    const float* d0   = (const float*)d_in[2];
    const float* W_vQ = (const float*)d_in[3];
    const float* W_vK = (const float*)d_in[4];
    const float* W_vV = (const float*)d_in[5];
    const float* W_eQ = (const float*)d_in[6];
    const float* W_eK = (const float*)d_in[7];
    const int*   v_idx = (const int*)d_in[8];
    const int*   e_idx = (const int*)d_in[9];
    float* out = (float*)d_out;

    float* S = nullptr;
    cudaGetSymbolAddress((void**)&S, g_scratch);
    float* vQ = S + OFF_VQ;
    float* vK = S + OFF_VK;
    float* vV = S + OFF_VV;
    float* eQ = S + OFF_EQ;
    float* eK = S + OFF_EK;
    float* y1 = S + OFF_Y1;
    float* y2 = S + OFF_Y2;
    float* z1 = S + OFF_Z1;

    const dim3 blk(256);

    // 1) projections: C = X @ W^T  (batch folded into rows)
    {
        dim3 gv(D_SZ / 128, (B_SZ * N_SZ) / 128, 1);
        sgemm_kernel<false, true><<<gv, blk>>>(x_v, W_vQ, vQ, 256, 256, 256, 256, 0, 0, 0);
        sgemm_kernel<false, true><<<gv, blk>>>(x_v, W_vK, vK, 256, 256, 256, 256, 0, 0, 0);
        sgemm_kernel<false, true><<<gv, blk>>>(x_v, W_vV, vV, 256, 256, 256, 256, 0, 0, 0);
        dim3 ge(D_SZ / 128, (B_SZ * M_SZ) / 128, 1);
        sgemm_kernel<false, true><<<ge, blk>>>(x_e, W_eQ, eQ, 256, 256, 256, 256, 0, 0, 0);
        sgemm_kernel<false, true><<<ge, blk>>>(x_e, W_eK, eK, 256, 256, 256, 256, 0, 0, 0);
    }

    // 2) per-head LayerNorm (in place)
    ln_heads_kernel<<<B_SZ * N_SZ, blk>>>(vQ);
    ln_heads_kernel<<<B_SZ * N_SZ, blk>>>(vK);
    ln_heads_kernel<<<B_SZ * M_SZ, blk>>>(eQ);
    ln_heads_kernel<<<B_SZ * M_SZ, blk>>>(eK);

    // 3) y1[b] = d0[b] (MxN) @ vV[b] (Nx256)
    {
        dim3 g1(D_SZ / 128, M_SZ / 128, B_SZ);
        sgemm_kernel<false, false><<<g1, blk>>>(
            d0, vV, y1, N_SZ, N_SZ, 256, 256,
            (size_t)M_SZ * N_SZ, (size_t)N_SZ * 256, (size_t)M_SZ * 256);
    }

    // 4) edge sparse attention: q=eQ, k=eK, values=y1, idx=e_idx -> y2
    sparse_attn_kernel<<<dim3(M_SZ, B_SZ), blk>>>(eQ, eK, y1, e_idx, y2, M_SZ);

    // 5) z1[b] = d0[b]^T (NxM) @ y2[b] (Mx256)
    {
        dim3 g2(D_SZ / 128, N_SZ / 128, B_SZ);
        sgemm_kernel<true, false><<<g2, blk>>>(
            d0, y2, z1, M_SZ, N_SZ, 256, 256,
            (size_t)M_SZ * N_SZ, (size_t)M_SZ * 256, (size_t)N_SZ * 256);
    }

    // 6) vertex sparse attention: q=v_K, k=v_Q (note swap), values=z1 -> out
    sparse_attn_kernel<<<dim3(N_SZ, B_SZ), blk>>>(vK, vQ, z1, v_idx, out, N_SZ);
}

// round 15
// speedup vs baseline: 1.0125x; 1.0125x over previous
#include <cuda_runtime.h>
#include <stdint.h>
#include <stddef.h>

// ---------------------------------------------------------------------------
// MeshMultiHeadHodgeAttentionVertices — fp32 exact implementation
//
// Shapes: B=2, N=4096, M=12288, H=8, D=256 (dk=32), KV=KE=16
// Layout convention: every activation is (batch, rows, 256) row-major with
// column c = h*32 + d  (== split_heads column block). This makes LayerNorm
// (per 32-col block), sparse attention (per 32-col block) and the final
// transpose+reshape all trivial.
//
// Pipeline:
//   1) vQ,vK,vV = x_v @ W^T   (GEMM, TB)     rows = B*N = 8192
//      eQ,eK    = x_e @ W^T   (GEMM, TB)     rows = B*M = 24576
//   2) LayerNorm(32) in-place on vQ,vK,eQ,eK
//   3) y1[b] = d0[b] @ vV[b]                 (GEMM NN, K=4096)
//   4) y2 = sparse_attn(q=eQ, k=eK, v=y1, e_idx)
//   5) z1[b] = d0[b]^T @ y2[b]               (GEMM TA, K=12288)
//   6) out = sparse_attn(q=vK, k=vQ, v=z1, v_idx)
//
// GEMM core: 128x128x8 tile, 256 threads, 8x8 per thread, accumulation via
// packed fma.rn.f32x2 (FFMA2) -> 2x the fp32 FFMA rate on sm_103a.
// ---------------------------------------------------------------------------

#define B_SZ 2
#define N_SZ 4096
#define M_SZ 12288
#define D_SZ 256

// scratch offsets (floats)
#define OFF_VQ 0ull
#define OFF_VK 2097152ull       //  B*N*256
#define OFF_VV 4194304ull
#define OFF_EQ 6291456ull       //  then B*M*256 blocks
#define OFF_EK 12582912ull
#define OFF_Y1 18874368ull
#define OFF_Y2 25165824ull
#define OFF_Z1 31457280ull
#define SCRATCH_FLOATS 33554432ull   // 128 MiB

__device__ float g_scratch[SCRATCH_FLOATS];

// ---- packed fp32x2 helpers (sm_103a FFMA2 via PTX) ------------------------
__device__ __forceinline__ unsigned long long splat2(float a) {
    unsigned int u = __float_as_uint(a);
    unsigned long long r;
    asm("mov.b64 %0, {%1, %1};" : "=l"(r) : "r"(u));
    return r;
}
__device__ __forceinline__ unsigned long long ffma2(unsigned long long a,
                                                    unsigned long long b,
                                                    unsigned long long c) {
    unsigned long long d;
    asm("fma.rn.f32x2 %0, %1, %2, %3;" : "=l"(d) : "l"(a), "l"(b), "l"(c));
    return d;
}

// ---------------------------------------------------------------------------
// Tiled GEMM:  C[i,j] = sum_k Aop[i,k] * Bop[k,j]
//   TA=false: A row-major (i,k), lda = row stride
//   TA=true : A stored (k,i), lda = stride per k  (i.e. C = A^T_storage @ B)
//   TB=false: B row-major (k,j), ldb = row stride
//   TB=true : B stored (j,k), ldb = row stride    (i.e. B = W^T)
// All dims must be multiples of the tile (they are, by construction).
// ---------------------------------------------------------------------------
template <bool TA, bool TB>
__global__ __launch_bounds__(256, 2)
void sgemm_kernel(const float* __restrict__ A, const float* __restrict__ B,
                  float* __restrict__ C, int K, int lda, int ldb, int ldc,
                  size_t sA, size_t sB, size_t sC)
{
    __shared__ float As[8][132];
    __shared__ float Bs[8][132];

    A += (size_t)blockIdx.z * sA;
    B += (size_t)blockIdx.z * sB;
    C += (size_t)blockIdx.z * sC;

    const int i0 = blockIdx.y * 128;
    const int j0 = blockIdx.x * 128;
    const int tid = threadIdx.x;
    const int tx = tid & 15;   // col group
    const int ty = tid >> 4;   // row group

    // acc[m][n] packs output pair (col even, col odd)
    unsigned long long acc[8][4];
#pragma unroll
    for (int m = 0; m < 8; ++m)
#pragma unroll
        for (int n = 0; n < 4; ++n) acc[m][n] = 0ull;

    for (int k0 = 0; k0 < K; k0 += 8) {
        // ---- load A tile (128 rows x 8 k) into As[k][row] ----
        if (!TA) {
            const int row = tid >> 1;
            const int kq  = (tid & 1) * 4;
            float4 av = *reinterpret_cast<const float4*>(
                A + (size_t)(i0 + row) * lda + k0 + kq);
            As[kq + 0][row] = av.x;
            As[kq + 1][row] = av.y;
            As[kq + 2][row] = av.z;
            As[kq + 3][row] = av.w;
        } else {
            const int kk = tid >> 5;
            const int ii = (tid & 31) * 4;
            *reinterpret_cast<float4*>(&As[kk][ii]) =
                *reinterpret_cast<const float4*>(
                    A + (size_t)(k0 + kk) * lda + i0 + ii);
        }
        // ---- load B tile (8 k x 128 cols) into Bs[k][col] ----
        if (!TB) {
            const int kk = tid >> 5;
            const int jj = (tid & 31) * 4;
            *reinterpret_cast<float4*>(&Bs[kk][jj]) =
                *reinterpret_cast<const float4*>(
                    B + (size_t)(k0 + kk) * ldb + j0 + jj);
        } else {
            const int col = tid >> 1;
            const int kq  = (tid & 1) * 4;
            float4 bv = *reinterpret_cast<const float4*>(
                B + (size_t)(j0 + col) * ldb + k0 + kq);
            Bs[kq + 0][col] = bv.x;
            Bs[kq + 1][col] = bv.y;
            Bs[kq + 2][col] = bv.z;
            Bs[kq + 3][col] = bv.w;
        }
        __syncthreads();

#pragma unroll
        for (int kk = 0; kk < 8; ++kk) {
            float4 a0 = *reinterpret_cast<const float4*>(&As[kk][ty * 4]);
            float4 a1 = *reinterpret_cast<const float4*>(&As[kk][64 + ty * 4]);
            ulonglong2 b0 = *reinterpret_cast<const ulonglong2*>(&Bs[kk][tx * 4]);
            ulonglong2 b1 = *reinterpret_cast<const ulonglong2*>(&Bs[kk][64 + tx * 4]);
            float a[8] = {a0.x, a0.y, a0.z, a0.w, a1.x, a1.y, a1.z, a1.w};
            unsigned long long bp[4] = {b0.x, b0.y, b1.x, b1.y};
#pragma unroll
            for (int m = 0; m < 8; ++m) {
                unsigned long long am = splat2(a[m]);
#pragma unroll
                for (int n = 0; n < 4; ++n)
                    acc[m][n] = ffma2(am, bp[n], acc[m][n]);
            }
        }
        __syncthreads();
    }

    // ---- epilogue: pairs are contiguous columns -> 8-byte stores ----
#pragma unroll
    for (int m = 0; m < 8; ++m) {
        const int gi = i0 + ((m < 4) ? (ty * 4 + m) : (64 + ty * 4 + (m - 4)));
#pragma unroll
        for (int n = 0; n < 4; ++n) {
            const int gj = j0 + ((n < 2) ? (tx * 4 + 2 * n)
                                         : (64 + tx * 4 + 2 * (n - 2)));
            *reinterpret_cast<unsigned long long*>(
                C + (size_t)gi * ldc + gj) = acc[m][n];
        }
    }
}

// ---------------------------------------------------------------------------
// Per-head LayerNorm over 32-element blocks, in place.
// One block per row, one warp per head.
// ---------------------------------------------------------------------------
__global__ __launch_bounds__(256)
void ln_heads_kernel(float* __restrict__ x)
{
    const size_t row = blockIdx.x;
    const int h = threadIdx.x >> 5;
    const int d = threadIdx.x & 31;
    float* p = x + row * 256 + h * 32;

    float v = p[d];
    float s = v;
#pragma unroll
    for (int o = 16; o > 0; o >>= 1) s += __shfl_xor_sync(0xffffffffu, s, o);
    const float mu = s * (1.0f / 32.0f);
    const float c = v - mu;
    float s2 = c * c;
#pragma unroll
    for (int o = 16; o > 0; o >>= 1) s2 += __shfl_xor_sync(0xffffffffu, s2, o);
    const float var = s2 * (1.0f / 32.0f);
    p[d] = c * rsqrtf(var + 1e-5f);
}

// ---------------------------------------------------------------------------
// Sparse attention: per (batch, row, head) warp.
//   scores_j = <q[row], k[idx[row][j]]> / sqrt(32);  softmax over 16;
//   out[row] = sum_j w_j * v[idx[row][j]]
// All tensors (B, R, 256) with head = 32-col block. 256 threads = 8 heads.
// ---------------------------------------------------------------------------
__global__ __launch_bounds__(256)
void sparse_attn_kernel(const float* __restrict__ q, const float* __restrict__ k,
                        const float* __restrict__ v, const int* __restrict__ idx,
                        float* __restrict__ out, int R)
{
    const int row = blockIdx.x;
    const size_t base = (size_t)blockIdx.y * (size_t)R * 256u;
    const int h = threadIdx.x >> 5;
    const int d = threadIdx.x & 31;
    const int col = h * 32 + d;

    const float qd = q[base + (size_t)row * 256 + col];

    int   g[16];
    float s[16];
#pragma unroll
    for (int j = 0; j < 16; ++j) {
        g[j] = __ldg(&idx[row * 16 + j]);
        const float kd = k[base + (size_t)g[j] * 256 + col];
        float p = qd * kd;
#pragma unroll
        for (int o = 16; o > 0; o >>= 1) p += __shfl_xor_sync(0xffffffffu, p, o);
        s[j] = p * 0.17677669529663687f;   // 1/sqrt(32)
    }

    float mx = s[0];
#pragma unroll
    for (int j = 1; j < 16; ++j) mx = fmaxf(mx, s[j]);
    float den = 0.0f;
#pragma unroll
    for (int j = 0; j < 16; ++j) { s[j] = expf(s[j] - mx); den += s[j]; }
    const float inv = 1.0f / den;

    float o = 0.0f;
#pragma unroll
    for (int j = 0; j < 16; ++j)
        o += s[j] * v[base + (size_t)g[j] * 256 + col];

    out[base + (size_t)row * 256 + col] = o * inv;
}

// ---------------------------------------------------------------------------
// Host launcher — graph-capturable: kernel launches only, default stream.
// Input order (metadata): x_v, x_e, d_0, W_vQ, W_vK, W_vV, W_eQ, W_eK,
//                         v_idx, e_idx. Output: float32 (B, N, 256).
// ---------------------------------------------------------------------------
extern "C" void kernel_launch(void* const* d_in, const int* in_sizes, int n_in,
                              void* d_out, int out_size)
{
    (void)in_sizes; (void)n_in; (void)out_size;
    const float* x_v  = (const float*)d_in[0];
    const float* x_e  = (const float*)d_in[1];
    const float* d0   = (const float*)d_in[2];
    const float* W_vQ = (const float*)d_in[3];
    const float* W_vK = (const float*)d_in[4];
    const float* W_vV = (const float*)d_in[5];
    const float* W_eQ = (const float*)d_in[6];
    const float* W_eK = (const float*)d_in[7];
    const int*   v_idx = (const int*)d_in[8];
    const int*   e_idx = (const int*)d_in[9];
    float* out = (float*)d_out;

    float* S = nullptr;
    cudaGetSymbolAddress((void**)&S, g_scratch);
    float* vQ = S + OFF_VQ;
    float* vK = S + OFF_VK;
    float* vV = S + OFF_VV;
    float* eQ = S + OFF_EQ;
    float* eK = S + OFF_EK;
    float* y1 = S + OFF_Y1;
    float* y2 = S + OFF_Y2;
    float* z1 = S + OFF_Z1;

    const dim3 blk(256);

    // 1) projections: C = X @ W^T  (batch folded into rows)
    {
        dim3 gv(D_SZ / 128, (B_SZ * N_SZ) / 128, 1);
        sgemm_kernel<false, true><<<gv, blk>>>(x_v, W_vQ, vQ, 256, 256, 256, 256, 0, 0, 0);
        sgemm_kernel<false, true><<<gv, blk>>>(x_v, W_vK, vK, 256, 256, 256, 256, 0, 0, 0);
        sgemm_kernel<false, true><<<gv, blk>>>(x_v, W_vV, vV, 256, 256, 256, 256, 0, 0, 0);
        dim3 ge(D_SZ / 128, (B_SZ * M_SZ) / 128, 1);
        sgemm_kernel<false, true><<<ge, blk>>>(x_e, W_eQ, eQ, 256, 256, 256, 256, 0, 0, 0);
        sgemm_kernel<false, true><<<ge, blk>>>(x_e, W_eK, eK, 256, 256, 256, 256, 0, 0, 0);
    }

    // 2) per-head LayerNorm (in place)
    ln_heads_kernel<<<B_SZ * N_SZ, blk>>>(vQ);
    ln_heads_kernel<<<B_SZ * N_SZ, blk>>>(vK);
    ln_heads_kernel<<<B_SZ * M_SZ, blk>>>(eQ);
    ln_heads_kernel<<<B_SZ * M_SZ, blk>>>(eK);

    // 3) y1[b] = d0[b] (MxN) @ vV[b] (Nx256)
    {
        dim3 g1(D_SZ / 128, M_SZ / 128, B_SZ);
        sgemm_kernel<false, false><<<g1, blk>>>(
            d0, vV, y1, N_SZ, N_SZ, 256, 256,
            (size_t)M_SZ * N_SZ, (size_t)N_SZ * 256, (size_t)M_SZ * 256);
    }

    // 4) edge sparse attention: q=eQ, k=eK, values=y1, idx=e_idx -> y2
    sparse_attn_kernel<<<dim3(M_SZ, B_SZ), blk>>>(eQ, eK, y1, e_idx, y2, M_SZ);

    // 5) z1[b] = d0[b]^T (NxM) @ y2[b] (Mx256)
    {
        dim3 g2(D_SZ / 128, N_SZ / 128, B_SZ);
        sgemm_kernel<true, false><<<g2, blk>>>(
            d0, y2, z1, M_SZ, N_SZ, 256, 256,
            (size_t)M_SZ * N_SZ, (size_t)M_SZ * 256, (size_t)N_SZ * 256);
    }

    // 6) vertex sparse attention: q=v_K, k=v_Q (note swap), values=z1 -> out
    sparse_attn_kernel<<<dim3(N_SZ, B_SZ), blk>>>(vK, vQ, z1, v_idx, out, N_SZ);
}

// round 17
// speedup vs baseline: 2.6313x; 2.5987x over previous
#include <cuda_runtime.h>
#include <cuda_bf16.h>
#include <stdint.h>
#include <stddef.h>

// ---------------------------------------------------------------------------
// MeshMultiHeadHodgeAttentionVertices — HMMA (mma.sync bf16, Ootomo 3-term
// split) implementation. tcgen05 is unavailable: the harness compiles via a
// compute_103 (non-'a') virtual arch, so only base-ISA tensor instructions
// (mma.sync / ldmatrix / cp.async) are legal. They still use the tensor pipe.
//
// B=2, N=4096, M=12288, H=8, D=256 (dk=32), KV=KE=16.
// All activations (batch, rows, 256) row-major; head h = cols [32h, 32h+32).
//
//   0) split weights to bf16 hi/lo; transpose+split d0 -> d0t [B,N,M]
//   1) vQ,vK,vV = x_v @ W^T ; eQ,eK = x_e @ W^T       hmma_gemm<fp32A>
//   2) LayerNorm(32) in place
//   3) transpose+split vV -> vVt [B,256,N]
//      y1[b] = d0[b] @ vV[b]         (K=4096)         hmma_gemm<fp32A>
//   4) y2 = sparse_attn(eQ,eK,y1,e_idx); transpose+split y2 -> y2t
//   5) z1[b] = d0[b]^T @ y2[b]       (K=12288)        hmma_gemm<bf16A>
//   6) out = sparse_attn(vK,vQ,z1,v_idx)
//
// GEMM: CTA tile 64(M) x 256(N) x 64(K). 8 warps = 2(m) x 4(n), warp tile
// 32x64. Double-buffered SMEM (SW128 swizzle, 128B rows), cp.async for bf16
// operands, LDG+split+STS for fp32 A. 3 mma per (m16,n8,k16): hi*hi + hi*lo
// + lo*hi, fp32 accumulators -> rel_err ~1e-5.
// ---------------------------------------------------------------------------

#define B_SZ 2
#define N_SZ 4096
#define M_SZ 12288

// scratch offsets (float units)
#define OFF_VQ      0ull
#define OFF_VK      2097152ull
#define OFF_VV      4194304ull
#define OFF_EQ      6291456ull
#define OFF_EK      12582912ull
#define OFF_Y1      18874368ull
#define OFF_Y2      25165824ull
#define OFF_Z1      31457280ull
#define OFF_VVT_HI  33554432ull     // bf16 [B,256,N]
#define OFF_VVT_LO  34603008ull
#define OFF_Y2T_HI  35651584ull     // bf16 [B,256,M]
#define OFF_Y2T_LO  38797312ull
#define OFF_WSP     41943040ull     // 5x (hi,lo) 256x256 bf16
#define OFF_D0T_HI  42270720ull     // bf16 [B,N,M]
#define OFF_D0T_LO  92602368ull
#define SCRATCH_FLOATS 142934016ull
__device__ float g_scratch[SCRATCH_FLOATS];

#define SWZ128(o) ((o) ^ (((o) >> 3) & 0x70))

__device__ __forceinline__ uint32_t smem_u32(const void* p) {
    uint32_t a;
    asm("{ .reg .u64 t; cvta.to.shared.u64 t, %1; cvt.u32.u64 %0, t; }"
        : "=r"(a) : "l"(p));
    return a;
}
__device__ __forceinline__ void cp16(uint32_t dst, const void* src) {
    asm volatile("cp.async.cg.shared.global [%0], [%1], 16;"
                 :: "r"(dst), "l"(src));
}
__device__ __forceinline__ void cp_commit() {
    asm volatile("cp.async.commit_group;" ::: "memory");
}
__device__ __forceinline__ void cp_wait1() {
    asm volatile("cp.async.wait_group 1;" ::: "memory");
}
__device__ __forceinline__ void cp_wait0() {
    asm volatile("cp.async.wait_group 0;" ::: "memory");
}
__device__ __forceinline__ void ldsm4(uint32_t& r0, uint32_t& r1,
                                      uint32_t& r2, uint32_t& r3, uint32_t a) {
    asm volatile("ldmatrix.sync.aligned.m8n8.x4.shared.b16 {%0,%1,%2,%3}, [%4];"
                 : "=r"(r0), "=r"(r1), "=r"(r2), "=r"(r3) : "r"(a));
}
__device__ __forceinline__ void mma16816(float* c, const uint32_t* a,
                                         const uint32_t* b) {
    asm volatile(
        "mma.sync.aligned.m16n8k16.row.col.f32.bf16.bf16.f32 "
        "{%0,%1,%2,%3}, {%4,%5,%6,%7}, {%8,%9}, {%0,%1,%2,%3};"
        : "+f"(c[0]), "+f"(c[1]), "+f"(c[2]), "+f"(c[3])
        : "r"(a[0]), "r"(a[1]), "r"(a[2]), "r"(a[3]), "r"(b[0]), "r"(b[1]));
}

// fp32 -> (hi, lo) bf16 pair, two values at a time
__device__ __forceinline__ void split2(float x, float y, uint32_t& h, uint32_t& l) {
    __nv_bfloat162 hb = __float22bfloat162_rn(make_float2(x, y));
    float2 hf = __bfloat1622float2(hb);
    __nv_bfloat162 lb = __float22bfloat162_rn(make_float2(x - hf.x, y - hf.y));
    h = *reinterpret_cast<uint32_t*>(&hb);
    l = *reinterpret_cast<uint32_t*>(&lb);
}

// ---------------------------------------------------------------------------
// HMMA GEMM:  C[i0+mi, nj] (+)= sum_k Aop[mi,k] * Bop[nj,k]
//   AFP32=true : A fp32 [rows, K] row-major, split in-kernel
//   AFP32=false: A pre-split bf16 hi/lo [rows, K]
//   B          : pre-split bf16 hi/lo [256, K]   (N fixed = 256, grid.x = 1)
// K multiple of 64. 256 threads.
// SMEM stage: Ah 8KB | Al 8KB | Bh 32KB | Bl 32KB = 80KB; 2 stages = 160KB.
// ---------------------------------------------------------------------------
#define GS_AH 0
#define GS_AL 8192
#define GS_BH 16384
#define GS_BL 49152
#define GS_SS 81920

template <bool AFP32>
__global__ __launch_bounds__(256, 1)
void hmma_gemm(const float* __restrict__ Af,
               const __nv_bfloat16* __restrict__ Ahi,
               const __nv_bfloat16* __restrict__ Alo,
               const __nv_bfloat16* __restrict__ Bhi,
               const __nv_bfloat16* __restrict__ Blo,
               float* __restrict__ C, int K, int lda, int ldb, int ldc,
               size_t sA, size_t sB, size_t sC)
{
    extern __shared__ char smem[];
    const uint32_t sb = smem_u32(smem);
    const int tid  = threadIdx.x;
    const int wid  = tid >> 5;
    const int lane = tid & 31;

    if constexpr (AFP32) { Af += blockIdx.z * sA; }
    else { Ahi += blockIdx.z * sA; Alo += blockIdx.z * sA; }
    Bhi += blockIdx.z * sB; Blo += blockIdx.z * sB;
    C   += blockIdx.z * sC;

    const int i0 = blockIdx.y * 64;

    // per-thread load mapping
    const int lrow = tid >> 2;              // 0..63
    const int lkq  = tid & 3;               // 16-elem k group
    // ldmatrix lane mapping
    const int wm = wid & 1;                 // m block (32 rows each)
    const int wn = wid >> 1;                // n block (64 cols each)
    const uint32_t aRowOff =
        (uint32_t)((wm * 32 + (lane & 15)) * 128) + (uint32_t)((lane >> 4) * 16);
    const int bsel = lane >> 3;
    const uint32_t bRowBase = (uint32_t)(wn * 64 + (bsel >> 1) * 8 + (lane & 7));
    const uint32_t bKb = (uint32_t)((bsel & 1) * 16);

    float acc[2][8][4];
#pragma unroll
    for (int i = 0; i < 2; ++i)
#pragma unroll
        for (int j = 0; j < 8; ++j)
#pragma unroll
            for (int q = 0; q < 4; ++q) acc[i][j][q] = 0.0f;

    const int NC = K >> 6;

    // ---- prologue: stage chunk 0 into buffer 0 ----
    {
        const int k0 = 0;
        const uint32_t ab = sb;             // buffer 0
        // B via cp.async
#pragma unroll
        for (int p = 0; p < 4; ++p) {
            const int row = lrow + 64 * p;
            const size_t go = (size_t)row * ldb + k0 + lkq * 16;
#pragma unroll
            for (int q = 0; q < 2; ++q) {
                const uint32_t off = SWZ128((uint32_t)(row * 128 + lkq * 32 + q * 16));
                cp16(ab + GS_BH + off, Bhi + go + q * 8);
                cp16(ab + GS_BL + off, Blo + go + q * 8);
            }
        }
        if constexpr (AFP32) {
            const float* gp = Af + (size_t)(i0 + lrow) * lda + k0 + lkq * 16;
            float4 f0 = *reinterpret_cast<const float4*>(gp);
            float4 f1 = *reinterpret_cast<const float4*>(gp + 4);
            float4 f2 = *reinterpret_cast<const float4*>(gp + 8);
            float4 f3 = *reinterpret_cast<const float4*>(gp + 12);
            uint32_t h[8], l[8];
            split2(f0.x, f0.y, h[0], l[0]); split2(f0.z, f0.w, h[1], l[1]);
            split2(f1.x, f1.y, h[2], l[2]); split2(f1.z, f1.w, h[3], l[3]);
            split2(f2.x, f2.y, h[4], l[4]); split2(f2.z, f2.w, h[5], l[5]);
            split2(f3.x, f3.y, h[6], l[6]); split2(f3.z, f3.w, h[7], l[7]);
            const uint32_t o0 = SWZ128((uint32_t)(lrow * 128 + lkq * 32));
            const uint32_t o1 = SWZ128((uint32_t)(lrow * 128 + lkq * 32 + 16));
            *reinterpret_cast<uint4*>(smem + GS_AH + o0) = make_uint4(h[0], h[1], h[2], h[3]);
            *reinterpret_cast<uint4*>(smem + GS_AH + o1) = make_uint4(h[4], h[5], h[6], h[7]);
            *reinterpret_cast<uint4*>(smem + GS_AL + o0) = make_uint4(l[0], l[1], l[2], l[3]);
            *reinterpret_cast<uint4*>(smem + GS_AL + o1) = make_uint4(l[4], l[5], l[6], l[7]);
        } else {
            const size_t go = (size_t)(i0 + lrow) * lda + k0 + lkq * 16;
#pragma unroll
            for (int q = 0; q < 2; ++q) {
                const uint32_t off = SWZ128((uint32_t)(lrow * 128 + lkq * 32 + q * 16));
                cp16(ab + GS_AH + off, Ahi + go + q * 8);
                cp16(ab + GS_AL + off, Alo + go + q * 8);
            }
        }
        cp_commit();
    }

    for (int c = 0; c < NC; ++c) {
        const bool more = (c + 1 < NC);
        const int cb = c & 1;
        const int nb = cb ^ 1;

        float4 f0, f1, f2, f3;
        if (more) {
            const int k1 = (c + 1) << 6;
            const uint32_t ab = sb + nb * GS_SS;
#pragma unroll
            for (int p = 0; p < 4; ++p) {
                const int row = lrow + 64 * p;
                const size_t go = (size_t)row * ldb + k1 + lkq * 16;
#pragma unroll
                for (int q = 0; q < 2; ++q) {
                    const uint32_t off = SWZ128((uint32_t)(row * 128 + lkq * 32 + q * 16));
                    cp16(ab + GS_BH + off, Bhi + go + q * 8);
                    cp16(ab + GS_BL + off, Blo + go + q * 8);
                }
            }
            if constexpr (AFP32) {
                const float* gp = Af + (size_t)(i0 + lrow) * lda + k1 + lkq * 16;
                f0 = *reinterpret_cast<const float4*>(gp);
                f1 = *reinterpret_cast<const float4*>(gp + 4);
                f2 = *reinterpret_cast<const float4*>(gp + 8);
                f3 = *reinterpret_cast<const float4*>(gp + 12);
            } else {
                const size_t go = (size_t)(i0 + lrow) * lda + k1 + lkq * 16;
#pragma unroll
                for (int q = 0; q < 2; ++q) {
                    const uint32_t off = SWZ128((uint32_t)(lrow * 128 + lkq * 32 + q * 16));
                    cp16(ab + GS_AH + off, Ahi + go + q * 8);
                    cp16(ab + GS_AL + off, Alo + go + q * 8);
                }
            }
            cp_commit();
            cp_wait1();
        } else {
            cp_wait0();
        }
        __syncthreads();

        // ---- compute chunk c from buffer cb ----
        {
            const uint32_t ab = sb + cb * GS_SS;
#pragma unroll
            for (int ks = 0; ks < 4; ++ks) {
                uint32_t ah[2][4], al[2][4];
#pragma unroll
                for (int mi = 0; mi < 2; ++mi) {
                    const uint32_t ao =
                        SWZ128(aRowOff + (uint32_t)(mi * 16 * 128) + (uint32_t)(ks * 32));
                    ldsm4(ah[mi][0], ah[mi][1], ah[mi][2], ah[mi][3], ab + GS_AH + ao);
                    ldsm4(al[mi][0], al[mi][1], al[mi][2], al[mi][3], ab + GS_AL + ao);
                }
#pragma unroll
                for (int half = 0; half < 2; ++half) {
                    uint32_t bh[4][2], bl[4][2];
#pragma unroll
                    for (int pp = 0; pp < 2; ++pp) {
                        const int njp = half * 2 + pp;   // pair of n8 blocks
                        const uint32_t bo = SWZ128(
                            (uint32_t)((bRowBase + njp * 16) * 128) +
                            (uint32_t)(ks * 32) + bKb);
                        ldsm4(bh[pp * 2][0], bh[pp * 2][1],
                              bh[pp * 2 + 1][0], bh[pp * 2 + 1][1], ab + GS_BH + bo);
                        ldsm4(bl[pp * 2][0], bl[pp * 2][1],
                              bl[pp * 2 + 1][0], bl[pp * 2 + 1][1], ab + GS_BL + bo);
                    }
#pragma unroll
                    for (int mi = 0; mi < 2; ++mi)
#pragma unroll
                        for (int nj = 0; nj < 4; ++nj) {
                            float* cc = acc[mi][half * 4 + nj];
                            mma16816(cc, ah[mi], bh[nj]);
                            mma16816(cc, ah[mi], bl[nj]);
                            mma16816(cc, al[mi], bh[nj]);
                        }
                }
            }
        }

        if (more) {
            if constexpr (AFP32) {
                char* st = smem + nb * GS_SS;
                uint32_t h[8], l[8];
                split2(f0.x, f0.y, h[0], l[0]); split2(f0.z, f0.w, h[1], l[1]);
                split2(f1.x, f1.y, h[2], l[2]); split2(f1.z, f1.w, h[3], l[3]);
                split2(f2.x, f2.y, h[4], l[4]); split2(f2.z, f2.w, h[5], l[5]);
                split2(f3.x, f3.y, h[6], l[6]); split2(f3.z, f3.w, h[7], l[7]);
                const uint32_t o0 = SWZ128((uint32_t)(lrow * 128 + lkq * 32));
                const uint32_t o1 = SWZ128((uint32_t)(lrow * 128 + lkq * 32 + 16));
                *reinterpret_cast<uint4*>(st + GS_AH + o0) = make_uint4(h[0], h[1], h[2], h[3]);
                *reinterpret_cast<uint4*>(st + GS_AH + o1) = make_uint4(h[4], h[5], h[6], h[7]);
                *reinterpret_cast<uint4*>(st + GS_AL + o0) = make_uint4(l[0], l[1], l[2], l[3]);
                *reinterpret_cast<uint4*>(st + GS_AL + o1) = make_uint4(l[4], l[5], l[6], l[7]);
            }
        }
        __syncthreads();
    }

    // ---- epilogue ----
    const int crow = i0 + wm * 32 + (lane >> 2);
    const int ccol = wn * 64 + (lane & 3) * 2;
#pragma unroll
    for (int mi = 0; mi < 2; ++mi)
#pragma unroll
        for (int nj = 0; nj < 8; ++nj) {
            float* cc = acc[mi][nj];
            float* p0 = C + (size_t)(crow + mi * 16) * ldc + ccol + nj * 8;
            float* p1 = p0 + 8 * (size_t)ldc;
            *reinterpret_cast<float2*>(p0) = make_float2(cc[0], cc[1]);
            *reinterpret_cast<float2*>(p1) = make_float2(cc[2], cc[3]);
        }
}

// ---------------------------------------------------------------------------
// transpose + split: in [R, C] fp32 (per batch) -> out_hi/lo [C, R] bf16
// ---------------------------------------------------------------------------
__global__ __launch_bounds__(256)
void tsplit_kernel(const float* __restrict__ in,
                   __nv_bfloat16* __restrict__ ohi, __nv_bfloat16* __restrict__ olo,
                   int R, int C, size_t sIn, size_t sOut)
{
    __shared__ float t[32][33];
    in  += blockIdx.z * sIn;
    ohi += blockIdx.z * sOut;
    olo += blockIdx.z * sOut;
    const int r0 = blockIdx.y * 32, c0 = blockIdx.x * 32;
    const int tid = threadIdx.x;
    {
        const int rr = tid >> 3, c4 = (tid & 7) * 4;
        float4 v = *reinterpret_cast<const float4*>(in + (size_t)(r0 + rr) * C + c0 + c4);
        t[rr][c4] = v.x; t[rr][c4 + 1] = v.y; t[rr][c4 + 2] = v.z; t[rr][c4 + 3] = v.w;
    }
    __syncthreads();
    {
        const int cc = tid >> 3, r4 = (tid & 7) * 4;
        uint32_t hp[2], lp[2];
#pragma unroll
        for (int i = 0; i < 2; ++i)
            split2(t[r4 + 2 * i][cc], t[r4 + 2 * i + 1][cc], hp[i], lp[i]);
        const size_t o = (size_t)(c0 + cc) * R + r0 + r4;
        *reinterpret_cast<uint2*>(ohi + o) = make_uint2(hp[0], hp[1]);
        *reinterpret_cast<uint2*>(olo + o) = make_uint2(lp[0], lp[1]);
    }
}

__global__ void split_kernel(const float* __restrict__ x,
                             __nv_bfloat16* __restrict__ hi,
                             __nv_bfloat16* __restrict__ lo, int n)
{
    int i = blockIdx.x * 256 + threadIdx.x;
    if (i < n) {
        float v = x[i];
        __nv_bfloat16 h = __float2bfloat16(v);
        hi[i] = h;
        lo[i] = __float2bfloat16(v - __bfloat162float(h));
    }
}

// ---------------------------------------------------------------------------
// Per-head LayerNorm(32), in place. One warp per head, 8 heads per row/block.
// ---------------------------------------------------------------------------
__global__ __launch_bounds__(256)
void ln_heads_kernel(float* __restrict__ x)
{
    const size_t row = blockIdx.x;
    const int h = threadIdx.x >> 5;
    const int d = threadIdx.x & 31;
    float* p = x + row * 256 + h * 32;

    float v = p[d];
    float s = v;
#pragma unroll
    for (int o = 16; o > 0; o >>= 1) s += __shfl_xor_sync(0xffffffffu, s, o);
    const float mu = s * (1.0f / 32.0f);
    const float c = v - mu;
    float s2 = c * c;
#pragma unroll
    for (int o = 16; o > 0; o >>= 1) s2 += __shfl_xor_sync(0xffffffffu, s2, o);
    p[d] = c * rsqrtf(s2 * (1.0f / 32.0f) + 1e-5f);
}

// ---------------------------------------------------------------------------
// Sparse attention over 16 gathered keys, per (batch, row, head) warp.
// ---------------------------------------------------------------------------
__global__ __launch_bounds__(256)
void sparse_attn_kernel(const float* __restrict__ q, const float* __restrict__ k,
                        const float* __restrict__ v, const int* __restrict__ idx,
                        float* __restrict__ out, int R)
{
    const int row = blockIdx.x;
    const size_t base = (size_t)blockIdx.y * (size_t)R * 256u;
    const int h = threadIdx.x >> 5;
    const int d = threadIdx.x & 31;
    const int col = h * 32 + d;

    const float qd = q[base + (size_t)row * 256 + col];

    int   g[16];
    float s[16];
#pragma unroll
    for (int j = 0; j < 16; ++j) {
        g[j] = __ldg(&idx[row * 16 + j]);
        float p = qd * k[base + (size_t)g[j] * 256 + col];
#pragma unroll
        for (int o = 16; o > 0; o >>= 1) p += __shfl_xor_sync(0xffffffffu, p, o);
        s[j] = p * 0.17677669529663687f;  // 1/sqrt(32)
    }
    float mx = s[0];
#pragma unroll
    for (int j = 1; j < 16; ++j) mx = fmaxf(mx, s[j]);
    float den = 0.0f;
#pragma unroll
    for (int j = 0; j < 16; ++j) { s[j] = expf(s[j] - mx); den += s[j]; }
    const float inv = 1.0f / den;

    float o = 0.0f;
#pragma unroll
    for (int j = 0; j < 16; ++j)
        o += s[j] * v[base + (size_t)g[j] * 256 + col];

    out[base + (size_t)row * 256 + col] = o * inv;
}

// ---------------------------------------------------------------------------
// Host launcher — default stream only, graph-capturable, allocation-free.
// Inputs: x_v, x_e, d_0, W_vQ, W_vK, W_vV, W_eQ, W_eK, v_idx, e_idx.
// ---------------------------------------------------------------------------
extern "C" void kernel_launch(void* const* d_in, const int* in_sizes, int n_in,
                              void* d_out, int out_size)
{
    (void)in_sizes; (void)n_in; (void)out_size;
    const float* x_v  = (const float*)d_in[0];
    const float* x_e  = (const float*)d_in[1];
    const float* d0   = (const float*)d_in[2];
    const float* Ws[5] = {(const float*)d_in[3], (const float*)d_in[4],
                          (const float*)d_in[5], (const float*)d_in[6],
                          (const float*)d_in[7]};
    const int* v_idx = (const int*)d_in[8];
    const int* e_idx = (const int*)d_in[9];
    float* out = (float*)d_out;

    float* S = nullptr;
    cudaGetSymbolAddress((void**)&S, g_scratch);
    float* vQ = S + OFF_VQ;  float* vK = S + OFF_VK;  float* vV = S + OFF_VV;
    float* eQ = S + OFF_EQ;  float* eK = S + OFF_EK;
    float* y1 = S + OFF_Y1;  float* y2 = S + OFF_Y2;  float* z1 = S + OFF_Z1;
    __nv_bfloat16* vVt_hi = (__nv_bfloat16*)(S + OFF_VVT_HI);
    __nv_bfloat16* vVt_lo = (__nv_bfloat16*)(S + OFF_VVT_LO);
    __nv_bfloat16* y2t_hi = (__nv_bfloat16*)(S + OFF_Y2T_HI);
    __nv_bfloat16* y2t_lo = (__nv_bfloat16*)(S + OFF_Y2T_LO);
    __nv_bfloat16* Wb     = (__nv_bfloat16*)(S + OFF_WSP);
    __nv_bfloat16* d0t_hi = (__nv_bfloat16*)(S + OFF_D0T_HI);
    __nv_bfloat16* d0t_lo = (__nv_bfloat16*)(S + OFF_D0T_LO);

    const int SMB = 2 * GS_SS;    // 163840 bytes
    cudaFuncSetAttribute((const void*)hmma_gemm<true>,
                         cudaFuncAttributeMaxDynamicSharedMemorySize, SMB);
    cudaFuncSetAttribute((const void*)hmma_gemm<false>,
                         cudaFuncAttributeMaxDynamicSharedMemorySize, SMB);

    const dim3 blk(256);

    // 0) weight splits + d0 transpose-split
    for (int w = 0; w < 5; ++w)
        split_kernel<<<256, blk>>>(Ws[w], Wb + w * 131072,
                                   Wb + w * 131072 + 65536, 65536);
    tsplit_kernel<<<dim3(N_SZ / 32, M_SZ / 32, B_SZ), blk>>>(
        d0, d0t_hi, d0t_lo, M_SZ, N_SZ,
        (size_t)M_SZ * N_SZ, (size_t)M_SZ * N_SZ);

    // 1) projections (batch folded into rows)
    float* pOut[5] = {vQ, vK, vV, eQ, eK};
    const float* pIn[5] = {x_v, x_v, x_v, x_e, x_e};
    const int pRows[5] = {B_SZ * N_SZ, B_SZ * N_SZ, B_SZ * N_SZ,
                          B_SZ * M_SZ, B_SZ * M_SZ};
    for (int w = 0; w < 5; ++w)
        hmma_gemm<true><<<dim3(1, pRows[w] / 64, 1), blk, SMB>>>(
            pIn[w], nullptr, nullptr,
            Wb + w * 131072, Wb + w * 131072 + 65536,
            pOut[w], 256, 256, 256, 256, 0, 0, 0);

    // 2) LayerNorm
    ln_heads_kernel<<<B_SZ * N_SZ, blk>>>(vQ);
    ln_heads_kernel<<<B_SZ * N_SZ, blk>>>(vK);
    ln_heads_kernel<<<B_SZ * M_SZ, blk>>>(eQ);
    ln_heads_kernel<<<B_SZ * M_SZ, blk>>>(eK);

    // 3) vV -> vVt ; y1[b] = d0[b] @ vV[b]
    tsplit_kernel<<<dim3(256 / 32, N_SZ / 32, B_SZ), blk>>>(
        vV, vVt_hi, vVt_lo, N_SZ, 256,
        (size_t)N_SZ * 256, (size_t)N_SZ * 256);
    hmma_gemm<true><<<dim3(1, M_SZ / 64, B_SZ), blk, SMB>>>(
        d0, nullptr, nullptr, vVt_hi, vVt_lo, y1,
        N_SZ, N_SZ, N_SZ, 256,
        (size_t)M_SZ * N_SZ, (size_t)256 * N_SZ, (size_t)M_SZ * 256);

    // 4) edge sparse attention, then y2 -> y2t
    sparse_attn_kernel<<<dim3(M_SZ, B_SZ), blk>>>(eQ, eK, y1, e_idx, y2, M_SZ);
    tsplit_kernel<<<dim3(256 / 32, M_SZ / 32, B_SZ), blk>>>(
        y2, y2t_hi, y2t_lo, M_SZ, 256,
        (size_t)M_SZ * 256, (size_t)M_SZ * 256);

    // 5) z1[b] = d0[b]^T @ y2[b]   (A = d0t, B = y2t, pre-split bf16)
    hmma_gemm<false><<<dim3(1, N_SZ / 64, B_SZ), blk, SMB>>>(
        nullptr, d0t_hi, d0t_lo, y2t_hi, y2t_lo, z1,
        M_SZ, M_SZ, M_SZ, 256,
        (size_t)N_SZ * M_SZ, (size_t)256 * M_SZ, (size_t)N_SZ * 256);

    // 6) vertex sparse attention: q=vK, k=vQ (reference swaps), values=z1
    sparse_attn_kernel<<<dim3(N_SZ, B_SZ), blk>>>(vK, vQ, z1, v_idx, out, N_SZ);
}